// round 16
// baseline (speedup 1.0000x reference)
#include <cuda_runtime.h>
#include <cuda_bf16.h>
#include <math.h>
#include <stdint.h>

// ---------------------------------------------------------------------------
// SRU 2-layer, SEQ=2048 BATCH=16 HID=1024.
// GEMMs via mma.sync bf16 (base ISA) with 3-way hi/lo split:
//   A@B ~= Ahi@Bhi + Alo@Bhi + Ahi@Blo   (fp32 accumulate)
// BOTH operands fragment-major in global memory; GEMM has no smem/barriers.
// CTA 128x128, 4 warps at 64x64, K-chunk 16, 2 CTAs/SM.
// Scans: 8-way chunked linear recurrence, all float4-wide; rlast fused into
// the layer-2 sweep1 launch as concurrent extra blocks.
// ---------------------------------------------------------------------------

#define SEQ   2048
#define BATCH 16
#define HID   1024
#define N3H   3072
#define MROWS (SEQ * BATCH)          // 32768
#define CHK   8
#define CLEN  (SEQ / CHK)            // 256
#define LANES 16384                  // BATCH*HID
#define NFRAG ((N3H / 16) * 64 * 32)     // B fragments (uint4) per split
#define AFRAG ((MROWS / 16) * 64 * 32)   // A fragments (uint4) per split

__device__ float   g_U   [(size_t)MROWS * N3H];
__device__ float   g_h   [(size_t)MROWS * HID];
__device__ uint4   g_Xhf [AFRAG];
__device__ uint4   g_Xlf [AFRAG];
__device__ uint4   g_Hhf [AFRAG];
__device__ uint4   g_Hlf [AFRAG];
__device__ uint4   g_W0hf[NFRAG];
__device__ uint4   g_W0lf[NFRAG];
__device__ uint4   g_W1hf[NFRAG];
__device__ uint4   g_W1lf[NFRAG];
__device__ float   g_rpart[8 * BATCH * HID];
__device__ float   g_P[CHK * LANES];
__device__ float   g_Q[CHK * LANES];

__device__ __forceinline__ float sigmoidf_(float z) {
    return 1.0f / (1.0f + expf(-z));
}
__device__ __forceinline__ void mma16816(float* d, const uint32_t* a, uint32_t b0, uint32_t b1) {
    asm volatile(
        "mma.sync.aligned.m16n8k16.row.col.f32.bf16.bf16.f32 "
        "{%0,%1,%2,%3}, {%4,%5,%6,%7}, {%8,%9}, {%0,%1,%2,%3};"
        : "+f"(d[0]), "+f"(d[1]), "+f"(d[2]), "+f"(d[3])
        : "r"(a[0]), "r"(a[1]), "r"(a[2]), "r"(a[3]), "r"(b0), "r"(b1));
}
__device__ __forceinline__ uint32_t packbf(float x, float y) {
    __nv_bfloat16 hx = __float2bfloat16(x), hy = __float2bfloat16(y);
    uint16_t ux = *(uint16_t*)&hx, uy = *(uint16_t*)&hy;
    return (uint32_t)ux | ((uint32_t)uy << 16);
}
__device__ __forceinline__ float bfres(float x) {
    __nv_bfloat16 h = __float2bfloat16(x);
    return x - __bfloat162float(h);
}

// A-fragment u32 address for the bf16 pair at (row m, cols k,k+1), k even.
// m16n8k16 A map: lane = (m%8)*4 + ((k%8)/2); regs a0..a3 by (m&8),(k&8).
__device__ __forceinline__ size_t afrag_addr(int mg, int kc, int m_lo, int k_lo) {
    int lane = ((m_lo & 7) << 2) | ((k_lo & 7) >> 1);
    int reg  = ((m_lo & 8) >> 3) | ((k_lo & 8) >> 2);
    return (((size_t)mg * 64 + kc) * 32 + lane) * 4 + reg;
}

// ---------------------------------------------------------------------------
// W prep -> fragment-major (B operand of m16n8k16).
// ---------------------------------------------------------------------------
__global__ __launch_bounds__(256) void splitW_frag(
    const float* __restrict__ W, uint4* __restrict__ Fhi, uint4* __restrict__ Flo)
{
    __shared__ float t[16][65];
    const int n0 = blockIdx.x * 64;
    const int kc = blockIdx.y;
    const int tid = threadIdx.x;
    {
        int r = tid >> 6, c = tid & 63;
        #pragma unroll
        for (int i = 0; i < 4; i++)
            t[r + i * 4][c] = W[(size_t)(kc * 16 + r + i * 4) * N3H + n0 + c];
    }
    __syncthreads();
    if (tid < 128) {
        int g  = tid >> 5;
        int l  = tid & 31;
        int ne = g * 16 + (l >> 2);
        int no = ne + 8;
        int k0 = (l & 3) * 2;
        float e0 = t[k0][ne], e1 = t[k0 + 1][ne], e2 = t[k0 + 8][ne], e3 = t[k0 + 9][ne];
        float o0 = t[k0][no], o1 = t[k0 + 1][no], o2 = t[k0 + 8][no], o3 = t[k0 + 9][no];
        uint4 hi, lo;
        hi.x = packbf(e0, e1); hi.y = packbf(e2, e3);
        hi.z = packbf(o0, o1); hi.w = packbf(o2, o3);
        lo.x = packbf(bfres(e0), bfres(e1)); lo.y = packbf(bfres(e2), bfres(e3));
        lo.z = packbf(bfres(o0), bfres(o1)); lo.w = packbf(bfres(o2), bfres(o3));
        size_t idx = ((size_t)(n0 / 16 + g) * 64 + kc) * 32 + l;
        Fhi[idx] = hi;
        Flo[idx] = lo;
    }
}

// X -> fragment-major hi/lo (A operand). One thread per (m, 4 k's).
__global__ __launch_bounds__(256) void splitX_frag(
    const float* __restrict__ X, uint32_t* __restrict__ Fhi, uint32_t* __restrict__ Flo)
{
    int id = blockIdx.x * 256 + threadIdx.x;     // 0 .. MROWS*256-1
    int m  = id >> 8;
    int k  = (id & 255) * 4;
    float4 v = *(const float4*)&X[(size_t)m * HID + k];
    size_t fa = afrag_addr(m >> 4, k >> 4, m & 15, k & 15);
    Fhi[fa]     = packbf(v.x, v.y);
    Fhi[fa + 4] = packbf(v.z, v.w);
    Flo[fa]     = packbf(bfres(v.x), bfres(v.y));
    Flo[fa + 4] = packbf(bfres(v.z), bfres(v.w));
}

// ---------------------------------------------------------------------------
// GEMM: C(M x N) = A(M x 1024) @ B^T, both operands fragment-major in global.
// CTA 128x128, 4 warps (2M x 2N) at 64x64, K-chunk 16. No smem, no barriers.
// (Unchanged from R15: 88.3% tensor.)
// ---------------------------------------------------------------------------
#define NCH 64

__global__ __launch_bounds__(128, 2) void gemm_mma3(
    const uint4* __restrict__ Ahf, const uint4* __restrict__ Alf,
    const uint4* __restrict__ Bhf, const uint4* __restrict__ Blf,
    float* __restrict__ C, int ldc)
{
    const int tid  = threadIdx.x;
    const int wid  = tid >> 5;
    const int lane = tid & 31;
    const int wm   = wid >> 1;
    const int wn   = wid & 1;
    const int m0   = blockIdx.y * 128;
    const int n0   = blockIdx.x * 128;

    const size_t aBase = (size_t)(m0 / 16 + wm * 4) * 2048 + lane;
    const size_t bBase = (size_t)(n0 / 16 + wn * 4) * 2048 + lane;
    const uint4* pAh = Ahf + aBase;
    const uint4* pAl = Alf + aBase;
    const uint4* pBh = Bhf + bBase;
    const uint4* pBl = Blf + bBase;

    float acc[4][8][4];
    #pragma unroll
    for (int i = 0; i < 4; i++)
        #pragma unroll
        for (int j = 0; j < 8; j++)
            #pragma unroll
            for (int q = 0; q < 4; q++) acc[i][j][q] = 0.0f;

    uint4 Ah[4], Bh[4];
    #pragma unroll
    for (int i = 0; i < 4; i++) { Ah[i] = pAh[i * 2048]; Bh[i] = pBh[i * 2048]; }

    for (int ch = 0; ch < NCH; ch++) {
        const int co = ch * 32;
        uint4 Al[4], Bl[4];
        #pragma unroll
        for (int i = 0; i < 4; i++) { Al[i] = pAl[i * 2048 + co]; Bl[i] = pBl[i * 2048 + co]; }

        // phase 1: Ah @ Bh
        #pragma unroll
        for (int mt = 0; mt < 4; mt++) {
            const uint32_t* a = (const uint32_t*)&Ah[mt];
            #pragma unroll
            for (int ng = 0; ng < 4; ng++) {
                mma16816(acc[mt][2 * ng],     a, Bh[ng].x, Bh[ng].y);
                mma16816(acc[mt][2 * ng + 1], a, Bh[ng].z, Bh[ng].w);
            }
        }

        uint4 Ahn[4], Bhn[4];
        const bool more = (ch + 1 < NCH);
        if (more) {
            #pragma unroll
            for (int i = 0; i < 4; i++) {
                Ahn[i] = pAh[i * 2048 + co + 32];
                Bhn[i] = pBh[i * 2048 + co + 32];
            }
        }

        // phase 2: Al @ Bh
        #pragma unroll
        for (int mt = 0; mt < 4; mt++) {
            const uint32_t* a = (const uint32_t*)&Al[mt];
            #pragma unroll
            for (int ng = 0; ng < 4; ng++) {
                mma16816(acc[mt][2 * ng],     a, Bh[ng].x, Bh[ng].y);
                mma16816(acc[mt][2 * ng + 1], a, Bh[ng].z, Bh[ng].w);
            }
        }
        // phase 3: Ah @ Bl
        #pragma unroll
        for (int mt = 0; mt < 4; mt++) {
            const uint32_t* a = (const uint32_t*)&Ah[mt];
            #pragma unroll
            for (int ng = 0; ng < 4; ng++) {
                mma16816(acc[mt][2 * ng],     a, Bl[ng].x, Bl[ng].y);
                mma16816(acc[mt][2 * ng + 1], a, Bl[ng].z, Bl[ng].w);
            }
        }

        #pragma unroll
        for (int i = 0; i < 4; i++) { Ah[i] = Ahn[i]; Bh[i] = Bhn[i]; }
    }

    #pragma unroll
    for (int mt = 0; mt < 4; mt++) {
        const int rbase = m0 + wm * 64 + mt * 16 + (lane >> 2);
        #pragma unroll
        for (int nt = 0; nt < 8; nt++) {
            const int col = n0 + wn * 64 + nt * 8 + (lane & 3) * 2;
            float* p0 = C + (size_t)rbase * ldc + col;
            float* p1 = C + (size_t)(rbase + 8) * ldc + col;
            *(float2*)p0 = make_float2(acc[mt][nt][0], acc[mt][nt][1]);
            *(float2*)p1 = make_float2(acc[mt][nt][2], acc[mt][nt][3]);
        }
    }
}

// ---------------------------------------------------------------------------
// Layer-1 chunked scan, sweep1 (float4-wide: one thread per 4 lanes).
// ---------------------------------------------------------------------------
__global__ __launch_bounds__(256) void scan1_sweep1(
    const float* __restrict__ U, const float* __restrict__ b,
    float* __restrict__ P, float* __restrict__ Q)
{
    int id = blockIdx.x * 256 + threadIdx.x;     // 0..32767
    int j  = id >> 12;
    int g4 = id & 4095;
    int bb = g4 >> 8;
    int hh = (g4 & 255) * 4;
    float4 bf = *(const float4*)&b[hh];

    size_t u = ((size_t)(j * CLEN) * BATCH + bb) * N3H + hh;
    float c0 = 0, c1 = 0, c2 = 0, c3 = 0;
    float p0 = 1, p1 = 1, p2 = 1, p3 = 1;
    #pragma unroll 4
    for (int t = 0; t < CLEN; t++) {
        float4 xt = *(const float4*)&U[u];
        float4 fz = *(const float4*)&U[u + HID];
        float f0 = sigmoidf_(fz.x + bf.x), f1 = sigmoidf_(fz.y + bf.y);
        float f2 = sigmoidf_(fz.z + bf.z), f3 = sigmoidf_(fz.w + bf.w);
        c0 = f0 * c0 + (1.0f - f0) * xt.x;  c1 = f1 * c1 + (1.0f - f1) * xt.y;
        c2 = f2 * c2 + (1.0f - f2) * xt.z;  c3 = f3 * c3 + (1.0f - f3) * xt.w;
        p0 *= f0; p1 *= f1; p2 *= f2; p3 *= f3;
        u += (size_t)BATCH * N3H;
    }
    size_t o = (size_t)j * LANES + bb * 1024 + hh;
    *(float4*)&P[o] = make_float4(p0, p1, p2, p3);
    *(float4*)&Q[o] = make_float4(c0, c1, c2, c3);
}

// sweep2: float4-wide; emits h (fp32) + fragment-major hi/lo (2 u32 pairs).
__global__ __launch_bounds__(256) void scan1_sweep2(
    const float* __restrict__ U, const float* __restrict__ X,
    const float* __restrict__ b, const float* __restrict__ P,
    const float* __restrict__ Q, float* __restrict__ H,
    uint32_t* __restrict__ Fhi, uint32_t* __restrict__ Flo)
{
    int id = blockIdx.x * 256 + threadIdx.x;     // 0..32767
    int j  = id >> 12;
    int g4 = id & 4095;
    int bb = g4 >> 8;
    int hh = (g4 & 255) * 4;
    float4 bf = *(const float4*)&b[hh];
    float4 br = *(const float4*)&b[HID + hh];

    float c0 = 0, c1 = 0, c2 = 0, c3 = 0;
    for (int i = 0; i < j; i++) {
        size_t o = (size_t)i * LANES + bb * 1024 + hh;
        float4 Pv = *(const float4*)&P[o];
        float4 Qv = *(const float4*)&Q[o];
        c0 = Pv.x * c0 + Qv.x;  c1 = Pv.y * c1 + Qv.y;
        c2 = Pv.z * c2 + Qv.z;  c3 = Pv.w * c3 + Qv.w;
    }

    size_t u  = ((size_t)(j * CLEN) * BATCH + bb) * N3H + hh;
    size_t xi = ((size_t)(j * CLEN) * BATCH + bb) * HID + hh;
    size_t fa = afrag_addr(j * CLEN, hh >> 4, bb, hh & 15);
    #pragma unroll 4
    for (int t = 0; t < CLEN; t++) {
        float4 xt = *(const float4*)&U[u];
        float4 fz = *(const float4*)&U[u + HID];
        float4 rz = *(const float4*)&U[u + 2 * HID];
        float f0 = sigmoidf_(fz.x + bf.x), f1 = sigmoidf_(fz.y + bf.y);
        float f2 = sigmoidf_(fz.z + bf.z), f3 = sigmoidf_(fz.w + bf.w);
        float r0 = sigmoidf_(rz.x + br.x), r1 = sigmoidf_(rz.y + br.y);
        float r2 = sigmoidf_(rz.z + br.z), r3 = sigmoidf_(rz.w + br.w);
        c0 = f0 * c0 + (1.0f - f0) * xt.x;  c1 = f1 * c1 + (1.0f - f1) * xt.y;
        c2 = f2 * c2 + (1.0f - f2) * xt.z;  c3 = f3 * c3 + (1.0f - f3) * xt.w;
        float4 x0 = *(const float4*)&X[xi];
        float h0 = r0 * c0 + (1.0f - r0) * x0.x;
        float h1 = r1 * c1 + (1.0f - r1) * x0.y;
        float h2 = r2 * c2 + (1.0f - r2) * x0.z;
        float h3 = r3 * c3 + (1.0f - r3) * x0.w;
        *(float4*)&H[xi] = make_float4(h0, h1, h2, h3);
        Fhi[fa]     = packbf(h0, h1);
        Fhi[fa + 4] = packbf(h2, h3);
        Flo[fa]     = packbf(bfres(h0), bfres(h1));
        Flo[fa + 4] = packbf(bfres(h2), bfres(h3));
        u  += (size_t)BATCH * N3H;
        xi += (size_t)BATCH * HID;
        fa += 64 * 32 * 4;
    }
}

// ---------------------------------------------------------------------------
// Layer-2 sweep1 (float4) FUSED with rlast split-K partials.
// Blocks [0,128): sweep1 over compact U2 (ld=2048: [xtilde | f]).
// Blocks [128,160): rlast — block rb covers n-tile (rb&3), k-slice (rb>>2);
//   A slice cached in smem, W streamed once, k-order identical to before.
// ---------------------------------------------------------------------------
__global__ __launch_bounds__(256) void scan2_s1_rlast(
    const float* __restrict__ U2, const float* __restrict__ b,
    float* __restrict__ P, float* __restrict__ Q,
    const float* __restrict__ A, const float* __restrict__ W,
    float* __restrict__ part)
{
    const int tid = threadIdx.x;
    if (blockIdx.x < 128) {
        int id = blockIdx.x * 256 + tid;
        int j  = id >> 12;
        int g4 = id & 4095;
        int bb = g4 >> 8;
        int hh = (g4 & 255) * 4;
        float4 bf = *(const float4*)&b[hh];

        size_t u = ((size_t)(j * CLEN) * BATCH + bb) * 2048 + hh;
        float c0 = 0, c1 = 0, c2 = 0, c3 = 0;
        float p0 = 1, p1 = 1, p2 = 1, p3 = 1;
        #pragma unroll 4
        for (int t = 0; t < CLEN; t++) {
            float4 xt = *(const float4*)&U2[u];
            float4 fz = *(const float4*)&U2[u + 1024];
            float f0 = sigmoidf_(fz.x + bf.x), f1 = sigmoidf_(fz.y + bf.y);
            float f2 = sigmoidf_(fz.z + bf.z), f3 = sigmoidf_(fz.w + bf.w);
            c0 = f0 * c0 + (1.0f - f0) * xt.x;  c1 = f1 * c1 + (1.0f - f1) * xt.y;
            c2 = f2 * c2 + (1.0f - f2) * xt.z;  c3 = f3 * c3 + (1.0f - f3) * xt.w;
            p0 *= f0; p1 *= f1; p2 *= f2; p3 *= f3;
            u += (size_t)BATCH * 2048;
        }
        size_t o = (size_t)j * LANES + bb * 1024 + hh;
        *(float4*)&P[o] = make_float4(p0, p1, p2, p3);
        *(float4*)&Q[o] = make_float4(c0, c1, c2, c3);
    } else {
        __shared__ float a_s[16][128];
        int rb = blockIdx.x - 128;       // 0..31
        int nt = rb & 3, ks = rb >> 2;
        for (int i = tid; i < 2048; i += 256) {
            int m = i >> 7, k = i & 127;
            a_s[m][k] = A[(size_t)m * HID + ks * 128 + k];
        }
        __syncthreads();
        int n = nt * 256 + tid;
        float s[16];
        #pragma unroll
        for (int m = 0; m < 16; m++) s[m] = 0.0f;
        const float* w = W + (size_t)(ks * 128) * N3H + 2 * HID + n;
        for (int k = 0; k < 128; k++) {
            float wv = w[(size_t)k * N3H];
            #pragma unroll
            for (int m = 0; m < 16; m++) s[m] += a_s[m][k] * wv;
        }
        #pragma unroll
        for (int m = 0; m < 16; m++)
            part[((size_t)ks * BATCH + m) * HID + n] = s[m];
    }
}

__global__ __launch_bounds__(256) void scan2_fin(
    const float* __restrict__ P, const float* __restrict__ Q,
    const float* __restrict__ H, const float* __restrict__ b,
    const float* __restrict__ part, float* __restrict__ out)
{
    int id = blockIdx.x * 256 + threadIdx.x;     // 0..4095
    int bb = id >> 8;
    int hh = (id & 255) * 4;
    int g  = bb * 1024 + hh;

    float c0 = 0, c1 = 0, c2 = 0, c3 = 0;
    #pragma unroll
    for (int i = 0; i < CHK; i++) {
        float4 Pv = *(const float4*)&P[(size_t)i * LANES + g];
        float4 Qv = *(const float4*)&Q[(size_t)i * LANES + g];
        c0 = Pv.x * c0 + Qv.x;  c1 = Pv.y * c1 + Qv.y;
        c2 = Pv.z * c2 + Qv.z;  c3 = Pv.w * c3 + Qv.w;
    }

    float4 rp = make_float4(0, 0, 0, 0);
    #pragma unroll
    for (int s = 0; s < 8; s++) {
        float4 pv = *(const float4*)&part[((size_t)s * BATCH + bb) * HID + hh];
        rp.x += pv.x; rp.y += pv.y; rp.z += pv.z; rp.w += pv.w;
    }
    float4 br = *(const float4*)&b[HID + hh];
    float r0 = sigmoidf_(rp.x + br.x), r1 = sigmoidf_(rp.y + br.y);
    float r2 = sigmoidf_(rp.z + br.z), r3 = sigmoidf_(rp.w + br.w);
    float4 x0 = *(const float4*)&H[(size_t)(SEQ - 1) * BATCH * HID + g];
    float4 ov;
    ov.x = r0 * c0 + (1.0f - r0) * x0.x;
    ov.y = r1 * c1 + (1.0f - r1) * x0.y;
    ov.z = r2 * c2 + (1.0f - r2) * x0.z;
    ov.w = r3 * c3 + (1.0f - r3) * x0.w;
    *(float4*)&out[g] = ov;
}

// ---------------------------------------------------------------------------
extern "C" void kernel_launch(void* const* d_in, const int* in_sizes, int n_in,
                              void* d_out, int out_size)
{
    const float* x  = (const float*)d_in[0];
    const float* W0 = (const float*)d_in[1];
    const float* b0 = (const float*)d_in[2];
    const float* W1 = (const float*)d_in[3];
    const float* b1 = (const float*)d_in[4];
    float* out = (float*)d_out;

    float *U, *Hbuf, *Rpart, *P, *Q;
    uint4 *Xhf, *Xlf, *Hhf, *Hlf, *W0hf, *W0lf, *W1hf, *W1lf;
    cudaGetSymbolAddress((void**)&U,     g_U);
    cudaGetSymbolAddress((void**)&Hbuf,  g_h);
    cudaGetSymbolAddress((void**)&Rpart, g_rpart);
    cudaGetSymbolAddress((void**)&P,     g_P);
    cudaGetSymbolAddress((void**)&Q,     g_Q);
    cudaGetSymbolAddress((void**)&Xhf,   g_Xhf);
    cudaGetSymbolAddress((void**)&Xlf,   g_Xlf);
    cudaGetSymbolAddress((void**)&Hhf,   g_Hhf);
    cudaGetSymbolAddress((void**)&Hlf,   g_Hlf);
    cudaGetSymbolAddress((void**)&W0hf,  g_W0hf);
    cudaGetSymbolAddress((void**)&W0lf,  g_W0lf);
    cudaGetSymbolAddress((void**)&W1hf,  g_W1hf);
    cudaGetSymbolAddress((void**)&W1lf,  g_W1lf);

    splitW_frag<<<dim3(N3H / 64, 64), 256>>>(W0, W0hf, W0lf);
    splitW_frag<<<dim3(N3H / 64, 64), 256>>>(W1, W1hf, W1lf);
    splitX_frag<<<MROWS, 256>>>(x, (uint32_t*)Xhf, (uint32_t*)Xlf);

    // Layer 1: U = X @ W0 (full 3072 cols)
    gemm_mma3<<<dim3(N3H / 128, MROWS / 128), 128>>>(Xhf, Xlf, W0hf, W0lf, U, N3H);
    scan1_sweep1<<<128, 256>>>(U, b0, P, Q);
    scan1_sweep2<<<128, 256>>>(U, x, b0, P, Q, Hbuf, (uint32_t*)Hhf, (uint32_t*)Hlf);

    // Layer 2: only xtilde+f cols (2048), compact ldc=2048
    gemm_mma3<<<dim3(2048 / 128, MROWS / 128), 128>>>(Hhf, Hlf, W1hf, W1lf, U, 2048);
    scan2_s1_rlast<<<160, 256>>>(U, b1, P, Q,
                                 Hbuf + (size_t)(SEQ - 1) * BATCH * HID, W1, Rpart);
    scan2_fin<<<16, 256>>>(P, Q, Hbuf, b1, Rpart, out);
}

// round 17
// speedup vs baseline: 1.2057x; 1.2057x over previous
#include <cuda_runtime.h>
#include <cuda_bf16.h>
#include <math.h>
#include <stdint.h>

// ---------------------------------------------------------------------------
// SRU 2-layer, SEQ=2048 BATCH=16 HID=1024.
// GEMMs via mma.sync bf16 (base ISA) with 3-way hi/lo split:
//   A@B ~= Ahi@Bhi + Alo@Bhi + Ahi@Blo   (fp32 accumulate)
// BOTH operands fragment-major in global memory; GEMM has no smem/barriers.
// CTA 128x128, 4 warps at 64x64, K-chunk 16, 2 CTAs/SM.
// Scans: 32-way chunked linear recurrence (CLEN=64), float4-wide at full
// occupancy; H fp32 written only at the last timestep; rlast fused into the
// layer-2 sweep1 launch.
// ---------------------------------------------------------------------------

#define SEQ   2048
#define BATCH 16
#define HID   1024
#define N3H   3072
#define MROWS (SEQ * BATCH)          // 32768
#define CHK   32
#define CLEN  (SEQ / CHK)            // 64
#define LANES 16384                  // BATCH*HID
#define NFRAG ((N3H / 16) * 64 * 32)     // B fragments (uint4) per split
#define AFRAG ((MROWS / 16) * 64 * 32)   // A fragments (uint4) per split

__device__ float   g_U   [(size_t)MROWS * N3H];
__device__ float   g_h   [(size_t)BATCH * HID];   // last-timestep h only
__device__ uint4   g_Xhf [AFRAG];
__device__ uint4   g_Xlf [AFRAG];
__device__ uint4   g_Hhf [AFRAG];
__device__ uint4   g_Hlf [AFRAG];
__device__ uint4   g_W0hf[NFRAG];
__device__ uint4   g_W0lf[NFRAG];
__device__ uint4   g_W1hf[NFRAG];
__device__ uint4   g_W1lf[NFRAG];
__device__ float   g_rpart[8 * BATCH * HID];
__device__ float   g_P[CHK * LANES];
__device__ float   g_Q[CHK * LANES];

__device__ __forceinline__ float sigmoidf_(float z) {
    return 1.0f / (1.0f + expf(-z));
}
__device__ __forceinline__ void mma16816(float* d, const uint32_t* a, uint32_t b0, uint32_t b1) {
    asm volatile(
        "mma.sync.aligned.m16n8k16.row.col.f32.bf16.bf16.f32 "
        "{%0,%1,%2,%3}, {%4,%5,%6,%7}, {%8,%9}, {%0,%1,%2,%3};"
        : "+f"(d[0]), "+f"(d[1]), "+f"(d[2]), "+f"(d[3])
        : "r"(a[0]), "r"(a[1]), "r"(a[2]), "r"(a[3]), "r"(b0), "r"(b1));
}
__device__ __forceinline__ uint32_t packbf(float x, float y) {
    __nv_bfloat16 hx = __float2bfloat16(x), hy = __float2bfloat16(y);
    uint16_t ux = *(uint16_t*)&hx, uy = *(uint16_t*)&hy;
    return (uint32_t)ux | ((uint32_t)uy << 16);
}
__device__ __forceinline__ float bfres(float x) {
    __nv_bfloat16 h = __float2bfloat16(x);
    return x - __bfloat162float(h);
}

// A-fragment u32 address for the bf16 pair at (row m, cols k,k+1), k even.
// m16n8k16 A map: lane = (m%8)*4 + ((k%8)/2); regs a0..a3 by (m&8),(k&8).
__device__ __forceinline__ size_t afrag_addr(int mg, int kc, int m_lo, int k_lo) {
    int lane = ((m_lo & 7) << 2) | ((k_lo & 7) >> 1);
    int reg  = ((m_lo & 8) >> 3) | ((k_lo & 8) >> 2);
    return (((size_t)mg * 64 + kc) * 32 + lane) * 4 + reg;
}

// ---------------------------------------------------------------------------
// W prep -> fragment-major (B operand of m16n8k16).
// ---------------------------------------------------------------------------
__global__ __launch_bounds__(256) void splitW_frag(
    const float* __restrict__ W, uint4* __restrict__ Fhi, uint4* __restrict__ Flo)
{
    __shared__ float t[16][65];
    const int n0 = blockIdx.x * 64;
    const int kc = blockIdx.y;
    const int tid = threadIdx.x;
    {
        int r = tid >> 6, c = tid & 63;
        #pragma unroll
        for (int i = 0; i < 4; i++)
            t[r + i * 4][c] = W[(size_t)(kc * 16 + r + i * 4) * N3H + n0 + c];
    }
    __syncthreads();
    if (tid < 128) {
        int g  = tid >> 5;
        int l  = tid & 31;
        int ne = g * 16 + (l >> 2);
        int no = ne + 8;
        int k0 = (l & 3) * 2;
        float e0 = t[k0][ne], e1 = t[k0 + 1][ne], e2 = t[k0 + 8][ne], e3 = t[k0 + 9][ne];
        float o0 = t[k0][no], o1 = t[k0 + 1][no], o2 = t[k0 + 8][no], o3 = t[k0 + 9][no];
        uint4 hi, lo;
        hi.x = packbf(e0, e1); hi.y = packbf(e2, e3);
        hi.z = packbf(o0, o1); hi.w = packbf(o2, o3);
        lo.x = packbf(bfres(e0), bfres(e1)); lo.y = packbf(bfres(e2), bfres(e3));
        lo.z = packbf(bfres(o0), bfres(o1)); lo.w = packbf(bfres(o2), bfres(o3));
        size_t idx = ((size_t)(n0 / 16 + g) * 64 + kc) * 32 + l;
        Fhi[idx] = hi;
        Flo[idx] = lo;
    }
}

// X -> fragment-major hi/lo (A operand). One thread per (m, 4 k's).
__global__ __launch_bounds__(256) void splitX_frag(
    const float* __restrict__ X, uint32_t* __restrict__ Fhi, uint32_t* __restrict__ Flo)
{
    int id = blockIdx.x * 256 + threadIdx.x;     // 0 .. MROWS*256-1
    int m  = id >> 8;
    int k  = (id & 255) * 4;
    float4 v = *(const float4*)&X[(size_t)m * HID + k];
    size_t fa = afrag_addr(m >> 4, k >> 4, m & 15, k & 15);
    Fhi[fa]     = packbf(v.x, v.y);
    Fhi[fa + 4] = packbf(v.z, v.w);
    Flo[fa]     = packbf(bfres(v.x), bfres(v.y));
    Flo[fa + 4] = packbf(bfres(v.z), bfres(v.w));
}

// ---------------------------------------------------------------------------
// GEMM: C(M x N) = A(M x 1024) @ B^T, both operands fragment-major in global.
// CTA 128x128, 4 warps (2M x 2N) at 64x64, K-chunk 16. No smem, no barriers.
// (Unchanged from R15: 88.3% tensor.)
// ---------------------------------------------------------------------------
#define NCH 64

__global__ __launch_bounds__(128, 2) void gemm_mma3(
    const uint4* __restrict__ Ahf, const uint4* __restrict__ Alf,
    const uint4* __restrict__ Bhf, const uint4* __restrict__ Blf,
    float* __restrict__ C, int ldc)
{
    const int tid  = threadIdx.x;
    const int wid  = tid >> 5;
    const int lane = tid & 31;
    const int wm   = wid >> 1;
    const int wn   = wid & 1;
    const int m0   = blockIdx.y * 128;
    const int n0   = blockIdx.x * 128;

    const size_t aBase = (size_t)(m0 / 16 + wm * 4) * 2048 + lane;
    const size_t bBase = (size_t)(n0 / 16 + wn * 4) * 2048 + lane;
    const uint4* pAh = Ahf + aBase;
    const uint4* pAl = Alf + aBase;
    const uint4* pBh = Bhf + bBase;
    const uint4* pBl = Blf + bBase;

    float acc[4][8][4];
    #pragma unroll
    for (int i = 0; i < 4; i++)
        #pragma unroll
        for (int j = 0; j < 8; j++)
            #pragma unroll
            for (int q = 0; q < 4; q++) acc[i][j][q] = 0.0f;

    uint4 Ah[4], Bh[4];
    #pragma unroll
    for (int i = 0; i < 4; i++) { Ah[i] = pAh[i * 2048]; Bh[i] = pBh[i * 2048]; }

    for (int ch = 0; ch < NCH; ch++) {
        const int co = ch * 32;
        uint4 Al[4], Bl[4];
        #pragma unroll
        for (int i = 0; i < 4; i++) { Al[i] = pAl[i * 2048 + co]; Bl[i] = pBl[i * 2048 + co]; }

        // phase 1: Ah @ Bh
        #pragma unroll
        for (int mt = 0; mt < 4; mt++) {
            const uint32_t* a = (const uint32_t*)&Ah[mt];
            #pragma unroll
            for (int ng = 0; ng < 4; ng++) {
                mma16816(acc[mt][2 * ng],     a, Bh[ng].x, Bh[ng].y);
                mma16816(acc[mt][2 * ng + 1], a, Bh[ng].z, Bh[ng].w);
            }
        }

        uint4 Ahn[4], Bhn[4];
        const bool more = (ch + 1 < NCH);
        if (more) {
            #pragma unroll
            for (int i = 0; i < 4; i++) {
                Ahn[i] = pAh[i * 2048 + co + 32];
                Bhn[i] = pBh[i * 2048 + co + 32];
            }
        }

        // phase 2: Al @ Bh
        #pragma unroll
        for (int mt = 0; mt < 4; mt++) {
            const uint32_t* a = (const uint32_t*)&Al[mt];
            #pragma unroll
            for (int ng = 0; ng < 4; ng++) {
                mma16816(acc[mt][2 * ng],     a, Bh[ng].x, Bh[ng].y);
                mma16816(acc[mt][2 * ng + 1], a, Bh[ng].z, Bh[ng].w);
            }
        }
        // phase 3: Ah @ Bl
        #pragma unroll
        for (int mt = 0; mt < 4; mt++) {
            const uint32_t* a = (const uint32_t*)&Ah[mt];
            #pragma unroll
            for (int ng = 0; ng < 4; ng++) {
                mma16816(acc[mt][2 * ng],     a, Bl[ng].x, Bl[ng].y);
                mma16816(acc[mt][2 * ng + 1], a, Bl[ng].z, Bl[ng].w);
            }
        }

        #pragma unroll
        for (int i = 0; i < 4; i++) { Ah[i] = Ahn[i]; Bh[i] = Bhn[i]; }
    }

    #pragma unroll
    for (int mt = 0; mt < 4; mt++) {
        const int rbase = m0 + wm * 64 + mt * 16 + (lane >> 2);
        #pragma unroll
        for (int nt = 0; nt < 8; nt++) {
            const int col = n0 + wn * 64 + nt * 8 + (lane & 3) * 2;
            float* p0 = C + (size_t)rbase * ldc + col;
            float* p1 = C + (size_t)(rbase + 8) * ldc + col;
            *(float2*)p0 = make_float2(acc[mt][nt][0], acc[mt][nt][1]);
            *(float2*)p1 = make_float2(acc[mt][nt][2], acc[mt][nt][3]);
        }
    }
}

// ---------------------------------------------------------------------------
// Layer-1 scan, sweep1: float4-wide, 32 chunks of 64 steps, 512 blocks.
// ---------------------------------------------------------------------------
__global__ __launch_bounds__(256) void scan1_sweep1(
    const float* __restrict__ U, const float* __restrict__ b,
    float* __restrict__ P, float* __restrict__ Q)
{
    int id = blockIdx.x * 256 + threadIdx.x;     // 0..131071
    int j  = id >> 12;                           // chunk 0..31
    int g4 = id & 4095;
    int bb = g4 >> 8;
    int hh = (g4 & 255) * 4;
    float4 bf = *(const float4*)&b[hh];

    size_t u = ((size_t)(j * CLEN) * BATCH + bb) * N3H + hh;
    float c0 = 0, c1 = 0, c2 = 0, c3 = 0;
    float p0 = 1, p1 = 1, p2 = 1, p3 = 1;
    #pragma unroll 4
    for (int t = 0; t < CLEN; t++) {
        float4 xt = *(const float4*)&U[u];
        float4 fz = *(const float4*)&U[u + HID];
        float f0 = sigmoidf_(fz.x + bf.x), f1 = sigmoidf_(fz.y + bf.y);
        float f2 = sigmoidf_(fz.z + bf.z), f3 = sigmoidf_(fz.w + bf.w);
        c0 = f0 * c0 + (1.0f - f0) * xt.x;  c1 = f1 * c1 + (1.0f - f1) * xt.y;
        c2 = f2 * c2 + (1.0f - f2) * xt.z;  c3 = f3 * c3 + (1.0f - f3) * xt.w;
        p0 *= f0; p1 *= f1; p2 *= f2; p3 *= f3;
        u += (size_t)BATCH * N3H;
    }
    size_t o = (size_t)j * LANES + bb * 1024 + hh;
    *(float4*)&P[o] = make_float4(p0, p1, p2, p3);
    *(float4*)&Q[o] = make_float4(c0, c1, c2, c3);
}

// sweep2: float4-wide, 512 blocks; emits fragment-major hi/lo; H fp32 only
// at the final global timestep.
__global__ __launch_bounds__(256) void scan1_sweep2(
    const float* __restrict__ U, const float* __restrict__ X,
    const float* __restrict__ b, const float* __restrict__ P,
    const float* __restrict__ Q, float* __restrict__ Hlast,
    uint32_t* __restrict__ Fhi, uint32_t* __restrict__ Flo)
{
    int id = blockIdx.x * 256 + threadIdx.x;     // 0..131071
    int j  = id >> 12;
    int g4 = id & 4095;
    int bb = g4 >> 8;
    int hh = (g4 & 255) * 4;
    float4 bf = *(const float4*)&b[hh];
    float4 br = *(const float4*)&b[HID + hh];

    float c0 = 0, c1 = 0, c2 = 0, c3 = 0;
    for (int i = 0; i < j; i++) {
        size_t o = (size_t)i * LANES + bb * 1024 + hh;
        float4 Pv = *(const float4*)&P[o];
        float4 Qv = *(const float4*)&Q[o];
        c0 = Pv.x * c0 + Qv.x;  c1 = Pv.y * c1 + Qv.y;
        c2 = Pv.z * c2 + Qv.z;  c3 = Pv.w * c3 + Qv.w;
    }

    size_t u  = ((size_t)(j * CLEN) * BATCH + bb) * N3H + hh;
    size_t xi = ((size_t)(j * CLEN) * BATCH + bb) * HID + hh;
    size_t fa = afrag_addr(j * CLEN, hh >> 4, bb, hh & 15);
    #pragma unroll 4
    for (int t = 0; t < CLEN; t++) {
        float4 xt = *(const float4*)&U[u];
        float4 fz = *(const float4*)&U[u + HID];
        float4 rz = *(const float4*)&U[u + 2 * HID];
        float f0 = sigmoidf_(fz.x + bf.x), f1 = sigmoidf_(fz.y + bf.y);
        float f2 = sigmoidf_(fz.z + bf.z), f3 = sigmoidf_(fz.w + bf.w);
        float r0 = sigmoidf_(rz.x + br.x), r1 = sigmoidf_(rz.y + br.y);
        float r2 = sigmoidf_(rz.z + br.z), r3 = sigmoidf_(rz.w + br.w);
        c0 = f0 * c0 + (1.0f - f0) * xt.x;  c1 = f1 * c1 + (1.0f - f1) * xt.y;
        c2 = f2 * c2 + (1.0f - f2) * xt.z;  c3 = f3 * c3 + (1.0f - f3) * xt.w;
        float4 x0 = *(const float4*)&X[xi];
        float h0 = r0 * c0 + (1.0f - r0) * x0.x;
        float h1 = r1 * c1 + (1.0f - r1) * x0.y;
        float h2 = r2 * c2 + (1.0f - r2) * x0.z;
        float h3 = r3 * c3 + (1.0f - r3) * x0.w;
        Fhi[fa]     = packbf(h0, h1);
        Fhi[fa + 4] = packbf(h2, h3);
        Flo[fa]     = packbf(bfres(h0), bfres(h1));
        Flo[fa + 4] = packbf(bfres(h2), bfres(h3));
        if (j == CHK - 1 && t == CLEN - 1)
            *(float4*)&Hlast[bb * HID + hh] = make_float4(h0, h1, h2, h3);
        u  += (size_t)BATCH * N3H;
        xi += (size_t)BATCH * HID;
        fa += 64 * 32 * 4;
    }
}

// ---------------------------------------------------------------------------
// Layer-2 sweep1 (float4, 512 blocks) FUSED with rlast split-K partials
// (blocks 512..543). A slice cached in smem, W streamed once, identical
// k-accumulation order to the standalone rlast kernel.
// ---------------------------------------------------------------------------
__global__ __launch_bounds__(256) void scan2_s1_rlast(
    const float* __restrict__ U2, const float* __restrict__ b,
    float* __restrict__ P, float* __restrict__ Q,
    const float* __restrict__ A, const float* __restrict__ W,
    float* __restrict__ part)
{
    const int tid = threadIdx.x;
    if (blockIdx.x < 512) {
        int id = blockIdx.x * 256 + tid;
        int j  = id >> 12;
        int g4 = id & 4095;
        int bb = g4 >> 8;
        int hh = (g4 & 255) * 4;
        float4 bf = *(const float4*)&b[hh];

        size_t u = ((size_t)(j * CLEN) * BATCH + bb) * 2048 + hh;
        float c0 = 0, c1 = 0, c2 = 0, c3 = 0;
        float p0 = 1, p1 = 1, p2 = 1, p3 = 1;
        #pragma unroll 4
        for (int t = 0; t < CLEN; t++) {
            float4 xt = *(const float4*)&U2[u];
            float4 fz = *(const float4*)&U2[u + 1024];
            float f0 = sigmoidf_(fz.x + bf.x), f1 = sigmoidf_(fz.y + bf.y);
            float f2 = sigmoidf_(fz.z + bf.z), f3 = sigmoidf_(fz.w + bf.w);
            c0 = f0 * c0 + (1.0f - f0) * xt.x;  c1 = f1 * c1 + (1.0f - f1) * xt.y;
            c2 = f2 * c2 + (1.0f - f2) * xt.z;  c3 = f3 * c3 + (1.0f - f3) * xt.w;
            p0 *= f0; p1 *= f1; p2 *= f2; p3 *= f3;
            u += (size_t)BATCH * 2048;
        }
        size_t o = (size_t)j * LANES + bb * 1024 + hh;
        *(float4*)&P[o] = make_float4(p0, p1, p2, p3);
        *(float4*)&Q[o] = make_float4(c0, c1, c2, c3);
    } else {
        __shared__ float a_s[16][128];
        int rb = blockIdx.x - 512;       // 0..31
        int nt = rb & 3, ks = rb >> 2;
        for (int i = tid; i < 2048; i += 256) {
            int m = i >> 7, k = i & 127;
            a_s[m][k] = A[(size_t)m * HID + ks * 128 + k];
        }
        __syncthreads();
        int n = nt * 256 + tid;
        float s[16];
        #pragma unroll
        for (int m = 0; m < 16; m++) s[m] = 0.0f;
        const float* w = W + (size_t)(ks * 128) * N3H + 2 * HID + n;
        for (int k = 0; k < 128; k++) {
            float wv = w[(size_t)k * N3H];
            #pragma unroll
            for (int m = 0; m < 16; m++) s[m] += a_s[m][k] * wv;
        }
        #pragma unroll
        for (int m = 0; m < 16; m++)
            part[((size_t)ks * BATCH + m) * HID + n] = s[m];
    }
}

__global__ __launch_bounds__(256) void scan2_fin(
    const float* __restrict__ P, const float* __restrict__ Q,
    const float* __restrict__ Hlast, const float* __restrict__ b,
    const float* __restrict__ part, float* __restrict__ out)
{
    int id = blockIdx.x * 256 + threadIdx.x;     // 0..4095
    int bb = id >> 8;
    int hh = (id & 255) * 4;
    int g  = bb * 1024 + hh;

    float c0 = 0, c1 = 0, c2 = 0, c3 = 0;
    #pragma unroll
    for (int i = 0; i < CHK; i++) {
        float4 Pv = *(const float4*)&P[(size_t)i * LANES + g];
        float4 Qv = *(const float4*)&Q[(size_t)i * LANES + g];
        c0 = Pv.x * c0 + Qv.x;  c1 = Pv.y * c1 + Qv.y;
        c2 = Pv.z * c2 + Qv.z;  c3 = Pv.w * c3 + Qv.w;
    }

    float4 rp = make_float4(0, 0, 0, 0);
    #pragma unroll
    for (int s = 0; s < 8; s++) {
        float4 pv = *(const float4*)&part[((size_t)s * BATCH + bb) * HID + hh];
        rp.x += pv.x; rp.y += pv.y; rp.z += pv.z; rp.w += pv.w;
    }
    float4 br = *(const float4*)&b[HID + hh];
    float r0 = sigmoidf_(rp.x + br.x), r1 = sigmoidf_(rp.y + br.y);
    float r2 = sigmoidf_(rp.z + br.z), r3 = sigmoidf_(rp.w + br.w);
    float4 x0 = *(const float4*)&Hlast[g];
    float4 ov;
    ov.x = r0 * c0 + (1.0f - r0) * x0.x;
    ov.y = r1 * c1 + (1.0f - r1) * x0.y;
    ov.z = r2 * c2 + (1.0f - r2) * x0.z;
    ov.w = r3 * c3 + (1.0f - r3) * x0.w;
    *(float4*)&out[g] = ov;
}

// ---------------------------------------------------------------------------
extern "C" void kernel_launch(void* const* d_in, const int* in_sizes, int n_in,
                              void* d_out, int out_size)
{
    const float* x  = (const float*)d_in[0];
    const float* W0 = (const float*)d_in[1];
    const float* b0 = (const float*)d_in[2];
    const float* W1 = (const float*)d_in[3];
    const float* b1 = (const float*)d_in[4];
    float* out = (float*)d_out;

    float *U, *Hlast, *Rpart, *P, *Q;
    uint4 *Xhf, *Xlf, *Hhf, *Hlf, *W0hf, *W0lf, *W1hf, *W1lf;
    cudaGetSymbolAddress((void**)&U,     g_U);
    cudaGetSymbolAddress((void**)&Hlast, g_h);
    cudaGetSymbolAddress((void**)&Rpart, g_rpart);
    cudaGetSymbolAddress((void**)&P,     g_P);
    cudaGetSymbolAddress((void**)&Q,     g_Q);
    cudaGetSymbolAddress((void**)&Xhf,   g_Xhf);
    cudaGetSymbolAddress((void**)&Xlf,   g_Xlf);
    cudaGetSymbolAddress((void**)&Hhf,   g_Hhf);
    cudaGetSymbolAddress((void**)&Hlf,   g_Hlf);
    cudaGetSymbolAddress((void**)&W0hf,  g_W0hf);
    cudaGetSymbolAddress((void**)&W0lf,  g_W0lf);
    cudaGetSymbolAddress((void**)&W1hf,  g_W1hf);
    cudaGetSymbolAddress((void**)&W1lf,  g_W1lf);

    splitW_frag<<<dim3(N3H / 64, 64), 256>>>(W0, W0hf, W0lf);
    splitW_frag<<<dim3(N3H / 64, 64), 256>>>(W1, W1hf, W1lf);
    splitX_frag<<<MROWS, 256>>>(x, (uint32_t*)Xhf, (uint32_t*)Xlf);

    // Layer 1: U = X @ W0 (full 3072 cols)
    gemm_mma3<<<dim3(N3H / 128, MROWS / 128), 128>>>(Xhf, Xlf, W0hf, W0lf, U, N3H);
    scan1_sweep1<<<512, 256>>>(U, b0, P, Q);
    scan1_sweep2<<<512, 256>>>(U, x, b0, P, Q, Hlast, (uint32_t*)Hhf, (uint32_t*)Hlf);

    // Layer 2: only xtilde+f cols (2048), compact ldc=2048
    gemm_mma3<<<dim3(2048 / 128, MROWS / 128), 128>>>(Hhf, Hlf, W1hf, W1lf, U, 2048);
    scan2_s1_rlast<<<544, 256>>>(U, b1, P, Q, Hlast, W1, Rpart);
    scan2_fin<<<16, 256>>>(P, Q, Hlast, b1, Rpart, out);
}